// round 1
// baseline (speedup 1.0000x reference)
#include <cuda_runtime.h>

#define NE 1600000
#define NV 100000
#define NLAYER 20
#define BN_EPS 1e-5f
#define NB 1024
#define NT 256

// Persistent device state (static allocations — no cudaMalloc).
__device__ float4 g_M[2][NV];        // node features, double buffered, padded to 16B
__device__ float  g_H[NE * 3];       // edge features (updated in place each layer)
__device__ float  g_z[NE * 3];       // mlp_v pre-activation scratch
__device__ float  g_stats[21 * 16];  // per-layer BN stats: [l*16+0..7]=e(sum4,sumsq4), [l*16+8..13]=v(sum3,sumsq3); slot 20 = head

__device__ __forceinline__ float wsum(float v) {
#pragma unroll
    for (int o = 16; o; o >>= 1) v += __shfl_xor_sync(0xffffffffu, v, o);
    return v;
}

// Reduce K per-thread partials across the block, one atomicAdd per block per channel.
template <int K>
__device__ __forceinline__ void block_atomic_add(float* dst, float* v) {
#pragma unroll
    for (int j = 0; j < K; j++) v[j] = wsum(v[j]);
    __shared__ float bs[K];
    if (threadIdx.x < K) bs[threadIdx.x] = 0.f;
    __syncthreads();
    if ((threadIdx.x & 31) == 0) {
#pragma unroll
        for (int j = 0; j < K; j++) atomicAdd(&bs[j], v[j]);
    }
    __syncthreads();
    if (threadIdx.x < K) atomicAdd(&dst[threadIdx.x], bs[threadIdx.x]);
}

// Copy inputs into persistent state (M padded to float4).
__global__ void k_init(const float* __restrict__ M, const float* __restrict__ H) {
    int t = blockIdx.x * blockDim.x + threadIdx.x;
    int s = gridDim.x * blockDim.x;
    for (int i = t; i < NV; i += s)
        g_M[0][i] = make_float4(M[3 * i], M[3 * i + 1], M[3 * i + 2], 0.f);
    for (int i = t; i < NE * 3; i += s) g_H[i] = H[i];
}

// Phase 1: BN stats of e_in @ we_w1 + we_b1 (4 channels). Also zeroes M_next.
__global__ void __launch_bounds__(NT)
k_estats(const int* __restrict__ src, const int* __restrict__ dst,
         const float* __restrict__ w1, const float* __restrict__ b1, int layer) {
    const float4* __restrict__ M = g_M[layer & 1];
    float4* Mn = g_M[(layer & 1) ^ 1];
    int t = blockIdx.x * blockDim.x + threadIdx.x;
    int s = gridDim.x * blockDim.x;
    for (int i = t; i < NV; i += s) Mn[i] = make_float4(0.f, 0.f, 0.f, 0.f);

    float acc[8] = {0.f, 0.f, 0.f, 0.f, 0.f, 0.f, 0.f, 0.f};
    for (int e = t; e < NE; e += s) {
        int is = __ldg(&src[e]);
        int id = __ldg(&dst[e]);
        float4 mi = __ldg(&M[id]);
        float4 mj = __ldg(&M[is]);
        float h0 = __ldg(&g_H[3 * e + 0]);
        float h1 = __ldg(&g_H[3 * e + 1]);
        float h2 = __ldg(&g_H[3 * e + 2]);
#pragma unroll
        for (int j = 0; j < 4; j++) {
            float y = __ldg(&b1[j])
                    + mi.x * __ldg(&w1[0 * 4 + j]) + mi.y * __ldg(&w1[1 * 4 + j]) + mi.z * __ldg(&w1[2 * 4 + j])
                    + mj.x * __ldg(&w1[3 * 4 + j]) + mj.y * __ldg(&w1[4 * 4 + j]) + mj.z * __ldg(&w1[5 * 4 + j])
                    + h0 * __ldg(&w1[6 * 4 + j]) + h1 * __ldg(&w1[7 * 4 + j]) + h2 * __ldg(&w1[8 * 4 + j]);
            acc[j] += y;
            acc[4 + j] += y * y;
        }
    }
    block_atomic_add<8>(g_stats + layer * 16, acc);
}

// Phase 2: apply e-BN -> Hn (written to g_H), compute z = v_in @ wv_w1 + b (to g_z), accumulate v-stats.
__global__ void __launch_bounds__(NT)
k_hn(const int* __restrict__ src, const int* __restrict__ dst,
     const float* __restrict__ w1, const float* __restrict__ b1,
     const float* __restrict__ g1, const float* __restrict__ be1,
     const float* __restrict__ w2, const float* __restrict__ b2,
     const float* __restrict__ wv1, const float* __restrict__ bv1, int layer) {
    const float* es = g_stats + layer * 16;
    float sc[4], sh[4];
#pragma unroll
    for (int j = 0; j < 4; j++) {
        float m = es[j] * (1.f / NE);
        float var = es[4 + j] * (1.f / NE) - m * m;
        float r = rsqrtf(var + BN_EPS);
        sc[j] = r * __ldg(&g1[j]);
        sh[j] = __ldg(&be1[j]) - m * sc[j];
    }
    const float4* __restrict__ M = g_M[layer & 1];
    int t = blockIdx.x * blockDim.x + threadIdx.x;
    int s = gridDim.x * blockDim.x;
    float vacc[6] = {0.f, 0.f, 0.f, 0.f, 0.f, 0.f};
    for (int e = t; e < NE; e += s) {
        int is = __ldg(&src[e]);
        int id = __ldg(&dst[e]);
        float4 mi = __ldg(&M[id]);
        float4 mj = __ldg(&M[is]);
        float h0 = __ldg(&g_H[3 * e + 0]);
        float h1 = __ldg(&g_H[3 * e + 1]);
        float h2 = __ldg(&g_H[3 * e + 2]);
        float tj[4];
#pragma unroll
        for (int j = 0; j < 4; j++) {
            float y = __ldg(&b1[j])
                    + mi.x * __ldg(&w1[0 * 4 + j]) + mi.y * __ldg(&w1[1 * 4 + j]) + mi.z * __ldg(&w1[2 * 4 + j])
                    + mj.x * __ldg(&w1[3 * 4 + j]) + mj.y * __ldg(&w1[4 * 4 + j]) + mj.z * __ldg(&w1[5 * 4 + j])
                    + h0 * __ldg(&w1[6 * 4 + j]) + h1 * __ldg(&w1[7 * 4 + j]) + h2 * __ldg(&w1[8 * 4 + j]);
            tj[j] = fmaxf(y * sc[j] + sh[j], 0.f);
        }
        float hn[3];
#pragma unroll
        for (int c = 0; c < 3; c++) {
            hn[c] = __ldg(&b2[c])
                  + tj[0] * __ldg(&w2[0 * 3 + c]) + tj[1] * __ldg(&w2[1 * 3 + c])
                  + tj[2] * __ldg(&w2[2 * 3 + c]) + tj[3] * __ldg(&w2[3 * 3 + c]);
            g_H[3 * e + c] = hn[c];
        }
#pragma unroll
        for (int c = 0; c < 3; c++) {
            float z = __ldg(&bv1[c])
                    + mi.x * __ldg(&wv1[0 * 3 + c]) + mi.y * __ldg(&wv1[1 * 3 + c]) + mi.z * __ldg(&wv1[2 * 3 + c])
                    + hn[0] * __ldg(&wv1[3 * 3 + c]) + hn[1] * __ldg(&wv1[4 * 3 + c]) + hn[2] * __ldg(&wv1[5 * 3 + c]);
            g_z[3 * e + c] = z;
            vacc[c] += z;
            vacc[3 + c] += z * z;
        }
    }
    block_atomic_add<6>(g_stats + layer * 16 + 8, vacc);
}

// Phase 3: apply v-BN, compute message, scatter-add into M_next.
__global__ void __launch_bounds__(NT)
k_scatter(const int* __restrict__ dst,
          const float* __restrict__ gv, const float* __restrict__ bev,
          const float* __restrict__ wv2, const float* __restrict__ bv2, int layer) {
    const float* vs = g_stats + layer * 16 + 8;
    float sc[3], sh[3];
#pragma unroll
    for (int c = 0; c < 3; c++) {
        float m = vs[c] * (1.f / NE);
        float var = vs[3 + c] * (1.f / NE) - m * m;
        float r = rsqrtf(var + BN_EPS);
        sc[c] = r * __ldg(&gv[c]);
        sh[c] = __ldg(&bev[c]) - m * sc[c];
    }
    float* Mn = (float*)&g_M[(layer & 1) ^ 1][0];
    int t = blockIdx.x * blockDim.x + threadIdx.x;
    int s = gridDim.x * blockDim.x;
    for (int e = t; e < NE; e += s) {
        int id = __ldg(&dst[e]);
        float t0 = fmaxf(__ldg(&g_z[3 * e + 0]) * sc[0] + sh[0], 0.f);
        float t1 = fmaxf(__ldg(&g_z[3 * e + 1]) * sc[1] + sh[1], 0.f);
        float t2 = fmaxf(__ldg(&g_z[3 * e + 2]) * sc[2] + sh[2], 0.f);
#pragma unroll
        for (int c = 0; c < 3; c++) {
            float msg = __ldg(&bv2[c])
                      + t0 * __ldg(&wv2[0 * 3 + c]) + t1 * __ldg(&wv2[1 * 3 + c]) + t2 * __ldg(&wv2[2 * 3 + c]);
            atomicAdd(&Mn[4 * id + c], msg);
        }
    }
}

// Head: stats of H @ out_w1 + out_b1 (3 channels).
__global__ void __launch_bounds__(NT)
kh_stats(const float* __restrict__ ow1, const float* __restrict__ ob1) {
    int t = blockIdx.x * blockDim.x + threadIdx.x;
    int s = gridDim.x * blockDim.x;
    float acc[6] = {0.f, 0.f, 0.f, 0.f, 0.f, 0.f};
    for (int e = t; e < NE; e += s) {
        float h0 = __ldg(&g_H[3 * e + 0]);
        float h1 = __ldg(&g_H[3 * e + 1]);
        float h2 = __ldg(&g_H[3 * e + 2]);
#pragma unroll
        for (int c = 0; c < 3; c++) {
            float y = __ldg(&ob1[c])
                    + h0 * __ldg(&ow1[0 * 3 + c]) + h1 * __ldg(&ow1[1 * 3 + c]) + h2 * __ldg(&ow1[2 * 3 + c]);
            acc[c] += y;
            acc[3 + c] += y * y;
        }
    }
    block_atomic_add<6>(g_stats + 20 * 16, acc);
}

// Head: apply BN + ReLU + Linear(3,2) + softmax -> out [E,2].
__global__ void __launch_bounds__(NT)
kh_out(const float* __restrict__ ow1, const float* __restrict__ ob1,
       const float* __restrict__ og, const float* __restrict__ obe,
       const float* __restrict__ ow2, const float* __restrict__ ob2,
       float* __restrict__ out) {
    const float* hs = g_stats + 20 * 16;
    float sc[3], sh[3];
#pragma unroll
    for (int c = 0; c < 3; c++) {
        float m = hs[c] * (1.f / NE);
        float var = hs[3 + c] * (1.f / NE) - m * m;
        float r = rsqrtf(var + BN_EPS);
        sc[c] = r * __ldg(&og[c]);
        sh[c] = __ldg(&obe[c]) - m * sc[c];
    }
    int t = blockIdx.x * blockDim.x + threadIdx.x;
    int s = gridDim.x * blockDim.x;
    for (int e = t; e < NE; e += s) {
        float h0 = __ldg(&g_H[3 * e + 0]);
        float h1 = __ldg(&g_H[3 * e + 1]);
        float h2 = __ldg(&g_H[3 * e + 2]);
        float tc[3];
#pragma unroll
        for (int c = 0; c < 3; c++) {
            float y = __ldg(&ob1[c])
                    + h0 * __ldg(&ow1[0 * 3 + c]) + h1 * __ldg(&ow1[1 * 3 + c]) + h2 * __ldg(&ow1[2 * 3 + c]);
            tc[c] = fmaxf(y * sc[c] + sh[c], 0.f);
        }
        float l0 = __ldg(&ob2[0]) + tc[0] * __ldg(&ow2[0]) + tc[1] * __ldg(&ow2[2]) + tc[2] * __ldg(&ow2[4]);
        float l1 = __ldg(&ob2[1]) + tc[0] * __ldg(&ow2[1]) + tc[1] * __ldg(&ow2[3]) + tc[2] * __ldg(&ow2[5]);
        float mx = fmaxf(l0, l1);
        float e0 = __expf(l0 - mx);  // use expf path; both logits shifted -> stable
        float e1 = __expf(l1 - mx);
        float inv = 1.f / (e0 + e1);
        out[2 * e + 0] = e0 * inv;
        out[2 * e + 1] = e1 * inv;
    }
}

extern "C" void kernel_launch(void* const* d_in, const int* in_sizes, int n_in,
                              void* d_out, int out_size) {
    const float* M     = (const float*)d_in[0];
    const float* H     = (const float*)d_in[1];
    const int*   ei    = (const int*)d_in[2];
    const int*   src   = ei;        // edge_index[0]
    const int*   dst   = ei + NE;   // edge_index[1]
    const float* we_w1 = (const float*)d_in[3];
    const float* we_b1 = (const float*)d_in[4];
    const float* we_g1 = (const float*)d_in[5];
    const float* we_be1= (const float*)d_in[6];
    const float* we_w2 = (const float*)d_in[7];
    const float* we_b2 = (const float*)d_in[8];
    const float* wv_w1 = (const float*)d_in[9];
    const float* wv_b1 = (const float*)d_in[10];
    const float* wv_g1 = (const float*)d_in[11];
    const float* wv_be1= (const float*)d_in[12];
    const float* wv_w2 = (const float*)d_in[13];
    const float* wv_b2 = (const float*)d_in[14];
    const float* out_w1= (const float*)d_in[15];
    const float* out_b1= (const float*)d_in[16];
    const float* out_g = (const float*)d_in[17];
    const float* out_be= (const float*)d_in[18];
    const float* out_w2= (const float*)d_in[19];
    const float* out_b2= (const float*)d_in[20];

    void* statsPtr = nullptr;
    cudaGetSymbolAddress(&statsPtr, g_stats);
    cudaMemsetAsync(statsPtr, 0, sizeof(float) * 21 * 16);

    k_init<<<NB, NT>>>(M, H);

    for (int l = 0; l < NLAYER; l++) {
        k_estats<<<NB, NT>>>(src, dst, we_w1, we_b1, l);
        k_hn<<<NB, NT>>>(src, dst, we_w1, we_b1, we_g1, we_be1, we_w2, we_b2,
                         wv_w1, wv_b1, l);
        k_scatter<<<NB, NT>>>(dst, wv_g1, wv_be1, wv_w2, wv_b2, l);
    }

    kh_stats<<<NB, NT>>>(out_w1, out_b1);
    kh_out<<<NB, NT>>>(out_w1, out_b1, out_g, out_be, out_w2, out_b2, (float*)d_out);
}

// round 2
// speedup vs baseline: 1.6446x; 1.6446x over previous
#include <cuda_runtime.h>
#include <cstddef>

#define NE 1600000
#define NV 100000
#define NLAYER 20
#define BN_EPS 1e-5f
#define NT 256
#define NBLK 1563               // ceil(NE/4 / NT)
#define STRIDE (NBLK * NT)      // 400128 ; 4*STRIDE >= NE

// ---------------- constant weights (copied in at launch, D2D) ----------------
struct CW {
    float we_w1[36], we_b1[4], we_g1[4], we_be1[4], we_w2[12], we_b2[3];
    float wv_w1[18], wv_b1[3], wv_g1[3], wv_be1[3], wv_w2[9], wv_b2[3];
    float ow1[9], ob1[3], og[3], obe[3], ow2[6], ob2[2];
};
__constant__ CW cw;

// ---------------- persistent device state (no cudaMalloc) --------------------
__device__ float4 g_M[2][NV];     // node features, double buffered, float4-padded
__device__ float  g_H[NE * 3];    // edge features
__device__ float4 g_Y[NE];        // phase-A pre-BN edge MLP output y[4]
__device__ float  g_Z[NE * 3];    // phase-A: mi-part of z ; phase-B: full z
__device__ float  g_stats[22 * 16]; // per layer: [l*16+0..7] e-stats, [l*16+8..13] v-stats; slot 20 = head

__device__ __forceinline__ float wsum(float v) {
#pragma unroll
    for (int o = 16; o; o >>= 1) v += __shfl_xor_sync(0xffffffffu, v, o);
    return v;
}

template <int K>
__device__ __forceinline__ void block_atomic_add(float* dst, float* v) {
#pragma unroll
    for (int j = 0; j < K; j++) v[j] = wsum(v[j]);
    __shared__ float bs[K];
    if (threadIdx.x < K) bs[threadIdx.x] = 0.f;
    __syncthreads();
    if ((threadIdx.x & 31) == 0) {
#pragma unroll
        for (int j = 0; j < K; j++) atomicAdd(&bs[j], v[j]);
    }
    __syncthreads();
    if (threadIdx.x < K) atomicAdd(&dst[threadIdx.x], bs[threadIdx.x]);
    __syncthreads();   // protect bs against next call
}

// ---------------- init: pack M to float4, copy H -----------------------------
__global__ void __launch_bounds__(NT)
k_init(const float* __restrict__ M, const float4* __restrict__ H4,
       float4* __restrict__ Mout, float4* __restrict__ Hout) {
    int t = blockIdx.x * NT + threadIdx.x;
    for (int i = t; i < NV; i += STRIDE)
        Mout[i] = make_float4(M[3 * i], M[3 * i + 1], M[3 * i + 2], 0.f);
    for (int i = t; i < (NE * 3) / 4; i += STRIDE) Hout[i] = H4[i];
}

// ---------------- phase A: gather, y = e_in@w1+b1, zm = mi-part of z ---------
__global__ void __launch_bounds__(NT)
k_A(const int* __restrict__ src, const int* __restrict__ dst,
    const float4* __restrict__ M, float4* __restrict__ Mn,
    const float* __restrict__ H, float4* __restrict__ Y,
    float* __restrict__ Z, float* __restrict__ statsOut) {
    int t = blockIdx.x * NT + threadIdx.x;
    for (int i = t; i < NV; i += STRIDE) Mn[i] = make_float4(0.f, 0.f, 0.f, 0.f);

    int e[4]; bool val[4]; int is[4], id[4];
#pragma unroll
    for (int k = 0; k < 4; k++) { e[k] = t + k * STRIDE; val[k] = e[k] < NE; }
#pragma unroll
    for (int k = 0; k < 4; k++) if (val[k]) { is[k] = __ldg(src + e[k]); id[k] = __ldg(dst + e[k]); }
    float4 mi[4], mj[4];
#pragma unroll
    for (int k = 0; k < 4; k++) if (val[k]) { mi[k] = __ldg(M + id[k]); mj[k] = __ldg(M + is[k]); }
    float h0[4], h1[4], h2[4];
#pragma unroll
    for (int k = 0; k < 4; k++) if (val[k]) {
        h0[k] = __ldg(H + 3 * e[k]); h1[k] = __ldg(H + 3 * e[k] + 1); h2[k] = __ldg(H + 3 * e[k] + 2);
    }
    float acc[8] = {0.f, 0.f, 0.f, 0.f, 0.f, 0.f, 0.f, 0.f};
#pragma unroll
    for (int k = 0; k < 4; k++) if (val[k]) {
        float y[4];
#pragma unroll
        for (int j = 0; j < 4; j++) {
            y[j] = cw.we_b1[j]
                 + mi[k].x * cw.we_w1[0 * 4 + j] + mi[k].y * cw.we_w1[1 * 4 + j] + mi[k].z * cw.we_w1[2 * 4 + j]
                 + mj[k].x * cw.we_w1[3 * 4 + j] + mj[k].y * cw.we_w1[4 * 4 + j] + mj[k].z * cw.we_w1[5 * 4 + j]
                 + h0[k] * cw.we_w1[6 * 4 + j] + h1[k] * cw.we_w1[7 * 4 + j] + h2[k] * cw.we_w1[8 * 4 + j];
            acc[j] += y[j];
            acc[4 + j] += y[j] * y[j];
        }
        Y[e[k]] = make_float4(y[0], y[1], y[2], y[3]);
#pragma unroll
        for (int c = 0; c < 3; c++) {
            Z[3 * e[k] + c] = cw.wv_b1[c]
                + mi[k].x * cw.wv_w1[0 * 3 + c] + mi[k].y * cw.wv_w1[1 * 3 + c] + mi[k].z * cw.wv_w1[2 * 3 + c];
        }
    }
    block_atomic_add<8>(statsOut, acc);
}

// ---------------- phase B: e-BN -> Hn -> full z, v-stats (pure streaming) ----
__global__ void __launch_bounds__(NT)
k_B(const float4* __restrict__ Y, float* __restrict__ Z, float* __restrict__ H,
    const float* __restrict__ statsIn, float* __restrict__ statsOut,
    float* __restrict__ headStats, int doHead) {
    float sc[4], sh[4];
#pragma unroll
    for (int j = 0; j < 4; j++) {
        float m = statsIn[j] * (1.f / NE);
        float v = statsIn[4 + j] * (1.f / NE) - m * m;
        float r = rsqrtf(v + BN_EPS);
        sc[j] = r * cw.we_g1[j];
        sh[j] = cw.we_be1[j] - m * sc[j];
    }
    int t = blockIdx.x * NT + threadIdx.x;
    int e[4]; bool val[4]; float4 y4[4]; float zm0[4], zm1[4], zm2[4];
#pragma unroll
    for (int k = 0; k < 4; k++) { e[k] = t + k * STRIDE; val[k] = e[k] < NE; }
#pragma unroll
    for (int k = 0; k < 4; k++) if (val[k]) y4[k] = __ldg(Y + e[k]);
#pragma unroll
    for (int k = 0; k < 4; k++) if (val[k]) {
        zm0[k] = Z[3 * e[k]]; zm1[k] = Z[3 * e[k] + 1]; zm2[k] = Z[3 * e[k] + 2];
    }
    float acc[6] = {0.f, 0.f, 0.f, 0.f, 0.f, 0.f};
    float hacc[6] = {0.f, 0.f, 0.f, 0.f, 0.f, 0.f};
#pragma unroll
    for (int k = 0; k < 4; k++) if (val[k]) {
        float tj[4];
        tj[0] = fmaxf(fmaf(y4[k].x, sc[0], sh[0]), 0.f);
        tj[1] = fmaxf(fmaf(y4[k].y, sc[1], sh[1]), 0.f);
        tj[2] = fmaxf(fmaf(y4[k].z, sc[2], sh[2]), 0.f);
        tj[3] = fmaxf(fmaf(y4[k].w, sc[3], sh[3]), 0.f);
        float hn[3];
#pragma unroll
        for (int c = 0; c < 3; c++) {
            hn[c] = cw.we_b2[c]
                  + tj[0] * cw.we_w2[0 * 3 + c] + tj[1] * cw.we_w2[1 * 3 + c]
                  + tj[2] * cw.we_w2[2 * 3 + c] + tj[3] * cw.we_w2[3 * 3 + c];
            H[3 * e[k] + c] = hn[c];
        }
        float zm[3] = {zm0[k], zm1[k], zm2[k]};
#pragma unroll
        for (int c = 0; c < 3; c++) {
            float z = zm[c]
                    + hn[0] * cw.wv_w1[3 * 3 + c] + hn[1] * cw.wv_w1[4 * 3 + c] + hn[2] * cw.wv_w1[5 * 3 + c];
            Z[3 * e[k] + c] = z;
            acc[c] += z;
            acc[3 + c] += z * z;
        }
        if (doHead) {
#pragma unroll
            for (int c = 0; c < 3; c++) {
                float yh = cw.ob1[c]
                         + hn[0] * cw.ow1[0 * 3 + c] + hn[1] * cw.ow1[1 * 3 + c] + hn[2] * cw.ow1[2 * 3 + c];
                hacc[c] += yh;
                hacc[3 + c] += yh * yh;
            }
        }
    }
    block_atomic_add<6>(statsOut, acc);
    if (doHead) block_atomic_add<6>(headStats, hacc);
}

// ---------------- phase C: v-BN -> message -> vec4 scatter-add ---------------
__global__ void __launch_bounds__(NT)
k_C(const int* __restrict__ dst, const float* __restrict__ Z,
    float4* __restrict__ Mn, const float* __restrict__ statsIn) {
    float sc[3], sh[3];
#pragma unroll
    for (int c = 0; c < 3; c++) {
        float m = statsIn[c] * (1.f / NE);
        float v = statsIn[3 + c] * (1.f / NE) - m * m;
        float r = rsqrtf(v + BN_EPS);
        sc[c] = r * cw.wv_g1[c];
        sh[c] = cw.wv_be1[c] - m * sc[c];
    }
    int t = blockIdx.x * NT + threadIdx.x;
    int e[4]; bool val[4]; int id[4]; float z0[4], z1[4], z2[4];
#pragma unroll
    for (int k = 0; k < 4; k++) { e[k] = t + k * STRIDE; val[k] = e[k] < NE; }
#pragma unroll
    for (int k = 0; k < 4; k++) if (val[k]) id[k] = __ldg(dst + e[k]);
#pragma unroll
    for (int k = 0; k < 4; k++) if (val[k]) {
        z0[k] = __ldg(Z + 3 * e[k]); z1[k] = __ldg(Z + 3 * e[k] + 1); z2[k] = __ldg(Z + 3 * e[k] + 2);
    }
    float zero = 0.f;
#pragma unroll
    for (int k = 0; k < 4; k++) if (val[k]) {
        float t0 = fmaxf(fmaf(z0[k], sc[0], sh[0]), 0.f);
        float t1 = fmaxf(fmaf(z1[k], sc[1], sh[1]), 0.f);
        float t2 = fmaxf(fmaf(z2[k], sc[2], sh[2]), 0.f);
        float m0 = cw.wv_b2[0] + t0 * cw.wv_w2[0] + t1 * cw.wv_w2[3] + t2 * cw.wv_w2[6];
        float m1 = cw.wv_b2[1] + t0 * cw.wv_w2[1] + t1 * cw.wv_w2[4] + t2 * cw.wv_w2[7];
        float m2 = cw.wv_b2[2] + t0 * cw.wv_w2[2] + t1 * cw.wv_w2[5] + t2 * cw.wv_w2[8];
        float* p = (float*)(Mn + id[k]);
        asm volatile("red.global.add.v4.f32 [%0], {%1,%2,%3,%4};"
                     :: "l"(p), "f"(m0), "f"(m1), "f"(m2), "f"(zero) : "memory");
    }
}

// ---------------- head: BN + ReLU + Linear(3,2) + softmax --------------------
__global__ void __launch_bounds__(NT)
kh_out(const float* __restrict__ H, const float* __restrict__ statsIn,
       float* __restrict__ out) {
    float sc[3], sh[3];
#pragma unroll
    for (int c = 0; c < 3; c++) {
        float m = statsIn[c] * (1.f / NE);
        float v = statsIn[3 + c] * (1.f / NE) - m * m;
        float r = rsqrtf(v + BN_EPS);
        sc[c] = r * cw.og[c];
        sh[c] = cw.obe[c] - m * sc[c];
    }
    int t = blockIdx.x * NT + threadIdx.x;
    int e[4]; bool val[4]; float h0[4], h1[4], h2[4];
#pragma unroll
    for (int k = 0; k < 4; k++) { e[k] = t + k * STRIDE; val[k] = e[k] < NE; }
#pragma unroll
    for (int k = 0; k < 4; k++) if (val[k]) {
        h0[k] = __ldg(H + 3 * e[k]); h1[k] = __ldg(H + 3 * e[k] + 1); h2[k] = __ldg(H + 3 * e[k] + 2);
    }
#pragma unroll
    for (int k = 0; k < 4; k++) if (val[k]) {
        float tc[3];
#pragma unroll
        for (int c = 0; c < 3; c++) {
            float y = cw.ob1[c]
                    + h0[k] * cw.ow1[0 * 3 + c] + h1[k] * cw.ow1[1 * 3 + c] + h2[k] * cw.ow1[2 * 3 + c];
            tc[c] = fmaxf(fmaf(y, sc[c], sh[c]), 0.f);
        }
        float l0 = cw.ob2[0] + tc[0] * cw.ow2[0] + tc[1] * cw.ow2[2] + tc[2] * cw.ow2[4];
        float l1 = cw.ob2[1] + tc[0] * cw.ow2[1] + tc[1] * cw.ow2[3] + tc[2] * cw.ow2[5];
        float mx = fmaxf(l0, l1);
        float e0 = __expf(l0 - mx);
        float e1 = __expf(l1 - mx);
        float inv = 1.f / (e0 + e1);
        float2 o = make_float2(e0 * inv, e1 * inv);
        ((float2*)out)[e[k]] = o;
    }
}

extern "C" void kernel_launch(void* const* d_in, const int* in_sizes, int n_in,
                              void* d_out, int out_size) {
    const float* M  = (const float*)d_in[0];
    const float* H  = (const float*)d_in[1];
    const int*   ei = (const int*)d_in[2];
    const int*   src = ei;
    const int*   dst = ei + NE;

    // Copy all weights into __constant__ struct (D2D async, graph-capturable).
    cudaMemcpyToSymbolAsync(cw, d_in[3],  36 * 4, offsetof(CW, we_w1), cudaMemcpyDeviceToDevice);
    cudaMemcpyToSymbolAsync(cw, d_in[4],   4 * 4, offsetof(CW, we_b1), cudaMemcpyDeviceToDevice);
    cudaMemcpyToSymbolAsync(cw, d_in[5],   4 * 4, offsetof(CW, we_g1), cudaMemcpyDeviceToDevice);
    cudaMemcpyToSymbolAsync(cw, d_in[6],   4 * 4, offsetof(CW, we_be1), cudaMemcpyDeviceToDevice);
    cudaMemcpyToSymbolAsync(cw, d_in[7],  12 * 4, offsetof(CW, we_w2), cudaMemcpyDeviceToDevice);
    cudaMemcpyToSymbolAsync(cw, d_in[8],   3 * 4, offsetof(CW, we_b2), cudaMemcpyDeviceToDevice);
    cudaMemcpyToSymbolAsync(cw, d_in[9],  18 * 4, offsetof(CW, wv_w1), cudaMemcpyDeviceToDevice);
    cudaMemcpyToSymbolAsync(cw, d_in[10],  3 * 4, offsetof(CW, wv_b1), cudaMemcpyDeviceToDevice);
    cudaMemcpyToSymbolAsync(cw, d_in[11],  3 * 4, offsetof(CW, wv_g1), cudaMemcpyDeviceToDevice);
    cudaMemcpyToSymbolAsync(cw, d_in[12],  3 * 4, offsetof(CW, wv_be1), cudaMemcpyDeviceToDevice);
    cudaMemcpyToSymbolAsync(cw, d_in[13],  9 * 4, offsetof(CW, wv_w2), cudaMemcpyDeviceToDevice);
    cudaMemcpyToSymbolAsync(cw, d_in[14],  3 * 4, offsetof(CW, wv_b2), cudaMemcpyDeviceToDevice);
    cudaMemcpyToSymbolAsync(cw, d_in[15],  9 * 4, offsetof(CW, ow1), cudaMemcpyDeviceToDevice);
    cudaMemcpyToSymbolAsync(cw, d_in[16],  3 * 4, offsetof(CW, ob1), cudaMemcpyDeviceToDevice);
    cudaMemcpyToSymbolAsync(cw, d_in[17],  3 * 4, offsetof(CW, og), cudaMemcpyDeviceToDevice);
    cudaMemcpyToSymbolAsync(cw, d_in[18],  3 * 4, offsetof(CW, obe), cudaMemcpyDeviceToDevice);
    cudaMemcpyToSymbolAsync(cw, d_in[19],  6 * 4, offsetof(CW, ow2), cudaMemcpyDeviceToDevice);
    cudaMemcpyToSymbolAsync(cw, d_in[20],  2 * 4, offsetof(CW, ob2), cudaMemcpyDeviceToDevice);

    float4 *gM0, *gM1; float *gH, *gZ, *gStats; float4* gY;
    {
        void* p;
        cudaGetSymbolAddress(&p, g_M);     gM0 = (float4*)p; gM1 = gM0 + NV;
        cudaGetSymbolAddress(&p, g_H);     gH = (float*)p;
        cudaGetSymbolAddress(&p, g_Y);     gY = (float4*)p;
        cudaGetSymbolAddress(&p, g_Z);     gZ = (float*)p;
        cudaGetSymbolAddress(&p, g_stats); gStats = (float*)p;
    }
    cudaMemsetAsync(gStats, 0, sizeof(float) * 22 * 16);

    k_init<<<NBLK, NT>>>(M, (const float4*)H, gM0, (float4*)gH);

    for (int l = 0; l < NLAYER; l++) {
        float4* Mc = (l & 1) ? gM1 : gM0;
        float4* Mn = (l & 1) ? gM0 : gM1;
        float* se = gStats + l * 16;      // e-BN stats (8)
        float* sv = gStats + l * 16 + 8;  // v-BN stats (6)
        k_A<<<NBLK, NT>>>(src, dst, Mc, Mn, gH, gY, gZ, se);
        k_B<<<NBLK, NT>>>(gY, gZ, gH, se, sv, gStats + 20 * 16, (l == NLAYER - 1) ? 1 : 0);
        k_C<<<NBLK, NT>>>(dst, gZ, Mn, sv);
    }
    kh_out<<<NBLK, NT>>>(gH, gStats + 20 * 16, (float*)d_out);
}